// round 7
// baseline (speedup 1.0000x reference)
#include <cuda_runtime.h>
#include <cuda_fp16.h>

// Problem constants (fixed by reference)
#define BB   32
#define NBX  6
#define HH   512
#define WW   512
#define PNp  512          // patch is PNp x PNp x 3
#define SCALE_F  0.5f
#define ASPECT_F 1.0f
#define MIN_PH_F 60.0f

struct __align__(16) PBox {
    int   y0, x0, h, w;
    float inv_h, inv_w;
    int   valid;
    int   pad;
};

// Quad-packed patch texel: full 2x2 bilinear footprint (clamped neighbors) fp16:
//   u[0]=(r00,r01) u[1]=(g00,g01) u[2]=(b00,b01)
//   u[3]=(r10,r11) u[4]=(g10,g11) u[5]=(b10,b11)  u[6..7]=pad
struct __align__(32) Quad { unsigned u[8]; };
__device__ Quad g_quad[PNp * PNp];       // 8 MB

// ---------------------------------------------------------------------------
// Prep: build quad-packed fp16 patch.
// ---------------------------------------------------------------------------
__global__ void __launch_bounds__(256)
prep_patch_kernel(const float* __restrict__ patch) {
    int i = blockIdx.x * blockDim.x + threadIdx.x;   // i = y*512 + x
    if (i >= PNp * PNp) return;
    int y  = i >> 9;
    int x  = i & (PNp - 1);
    int yh = min(y + 1, PNp - 1);
    int xh = min(x + 1, PNp - 1);

    const float* p00 = patch + ((size_t)y  * PNp + x ) * 3;
    const float* p01 = patch + ((size_t)y  * PNp + xh) * 3;
    const float* p10 = patch + ((size_t)yh * PNp + x ) * 3;
    const float* p11 = patch + ((size_t)yh * PNp + xh) * 3;

    __half2 r0 = __floats2half2_rn(__ldg(p00 + 0), __ldg(p01 + 0));
    __half2 g0 = __floats2half2_rn(__ldg(p00 + 1), __ldg(p01 + 1));
    __half2 b0 = __floats2half2_rn(__ldg(p00 + 2), __ldg(p01 + 2));
    __half2 r1 = __floats2half2_rn(__ldg(p10 + 0), __ldg(p11 + 0));
    __half2 g1 = __floats2half2_rn(__ldg(p10 + 1), __ldg(p11 + 1));
    __half2 b1 = __floats2half2_rn(__ldg(p10 + 2), __ldg(p11 + 2));

    Quad q;
    q.u[0] = *(const unsigned*)&r0;
    q.u[1] = *(const unsigned*)&g0;
    q.u[2] = *(const unsigned*)&b0;
    q.u[3] = *(const unsigned*)&r1;
    q.u[4] = *(const unsigned*)&g1;
    q.u[5] = *(const unsigned*)&b1;
    q.u[6] = 0; q.u[7] = 0;
    g_quad[i] = q;
}

// 256-bit loads/stores (sm_100+)
__device__ __forceinline__ void ldg256_nc(const void* p, unsigned r[8]) {
    asm volatile("ld.global.nc.v8.b32 {%0,%1,%2,%3,%4,%5,%6,%7}, [%8];"
                 : "=r"(r[0]), "=r"(r[1]), "=r"(r[2]), "=r"(r[3]),
                   "=r"(r[4]), "=r"(r[5]), "=r"(r[6]), "=r"(r[7])
                 : "l"(p));
}
__device__ __forceinline__ void ldg256_cs(const void* p, float r[8]) {
    asm volatile("ld.global.cs.v8.f32 {%0,%1,%2,%3,%4,%5,%6,%7}, [%8];"
                 : "=f"(r[0]), "=f"(r[1]), "=f"(r[2]), "=f"(r[3]),
                   "=f"(r[4]), "=f"(r[5]), "=f"(r[6]), "=f"(r[7])
                 : "l"(p));
}
__device__ __forceinline__ void stg256_cs(void* p, const float r[8]) {
    asm volatile("st.global.cs.v8.f32 [%0], {%1,%2,%3,%4,%5,%6,%7,%8};"
                 :: "l"(p),
                    "f"(r[0]), "f"(r[1]), "f"(r[2]), "f"(r[3]),
                    "f"(r[4]), "f"(r[5]), "f"(r[6]), "f"(r[7])
                 : "memory");
}

// ---------------------------------------------------------------------------
// Main: one thread per 8 consecutive pixels (24 floats = 3 x 256-bit).
// Each block covers 2048 contiguous pixels of ONE image (128 blocks/image).
// ---------------------------------------------------------------------------
__global__ void __launch_bounds__(256)
paste_kernel(const float* __restrict__ img,
             const float* __restrict__ boxes,
             float* __restrict__ out) {
    __shared__ PBox sbox[NBX];
    int b = blockIdx.x >> 7;           // 128 blocks per image
    if (threadIdx.x < NBX) {
        const float* bx = boxes + ((size_t)b * NBX + threadIdx.x) * 4;
        float ymin = __ldg(bx + 0), xmin = __ldg(bx + 1);
        float ymax = __ldg(bx + 2), xmax = __ldg(bx + 3);
        float h = ymax - ymin;
        float w = xmax - xmin;
        float pw = h * SCALE_F;
        float ph = ASPECT_F * pw;
        float oy = ymin + h * 0.5f;
        float ox = xmin + w * 0.5f;
        float yp = fmaxf(oy - ph * 0.5f, 0.0f);
        float xp = fmaxf(ox - pw * 0.5f, 0.0f);
        if (yp + ph > (float)HH) yp = (float)HH - ph;
        if (xp + pw > (float)WW) xp = (float)WW - pw;
        PBox pb;
        pb.y0 = (int)yp;
        pb.x0 = (int)xp;
        pb.h  = (int)ph;
        pb.w  = (int)pw;
        pb.inv_h = (float)PNp / fmaxf((float)pb.h, 1.0f);
        pb.inv_w = (float)PNp / fmaxf((float)pb.w, 1.0f);
        pb.valid = (ph > MIN_PH_F) ? 1 : 0;
        pb.pad = 0;
        sbox[threadIdx.x] = pb;
    }
    __syncthreads();

    int t  = blockIdx.x * blockDim.x + threadIdx.x;
    int p0 = t << 3;                   // first pixel index (8 per thread)
    int rem = p0 & ((1 << 18) - 1);    // within-image index
    int y   = rem >> 9;                // W = 2^9
    int x   = rem & (WW - 1);          // multiple of 8, within one row

    // Find topmost covering box per pixel
    int cov[8];
    #pragma unroll
    for (int k = 0; k < 8; ++k) cov[k] = -1;
    #pragma unroll
    for (int n = NBX - 1; n >= 0; --n) {
        PBox pb = sbox[n];
        if (!pb.valid) continue;
        int dy = y - pb.y0;
        if ((unsigned)dy >= (unsigned)pb.h) continue;
        int dx0 = x - pb.x0;
        #pragma unroll
        for (int k = 0; k < 8; ++k) {
            if (cov[k] < 0 && (unsigned)(dx0 + k) < (unsigned)pb.w) cov[k] = n;
        }
    }

    float px[24];                       // 8 px * rgb, pixel-major
    bool anyuncov = false;
    #pragma unroll
    for (int k = 0; k < 8; ++k) anyuncov |= (cov[k] < 0);

    const float* ibase = img + (size_t)p0 * 3;
    if (anyuncov) {
        ldg256_cs(ibase +  0, px +  0);
        ldg256_cs(ibase +  8, px +  8);
        ldg256_cs(ibase + 16, px + 16);
    }

    #pragma unroll
    for (int k = 0; k < 8; ++k) {
        if (cov[k] < 0) continue;
        PBox pb = sbox[cov[k]];
        int dy = y - pb.y0;
        int dx = (x + k) - pb.x0;

        float sy = ((float)dy + 0.5f) * pb.inv_h - 0.5f;
        float sx = ((float)dx + 0.5f) * pb.inv_w - 0.5f;
        sy = fminf(fmaxf(sy, 0.0f), (float)(PNp - 1));
        sx = fminf(fmaxf(sx, 0.0f), (float)(PNp - 1));

        int   yl = (int)floorf(sy);
        int   xl = (int)floorf(sx);
        float wy = sy - (float)yl;
        float wx = sx - (float)xl;

        unsigned q[8];
        ldg256_nc(&g_quad[yl * PNp + xl], q);

        float2 r0 = __half22float2(*(const __half2*)&q[0]);  // (r00, r01)
        float2 g0 = __half22float2(*(const __half2*)&q[1]);
        float2 b0 = __half22float2(*(const __half2*)&q[2]);
        float2 r1 = __half22float2(*(const __half2*)&q[3]);  // (r10, r11)
        float2 g1 = __half22float2(*(const __half2*)&q[4]);
        float2 b1 = __half22float2(*(const __half2*)&q[5]);

        float omwy = 1.0f - wy;
        float omwx = 1.0f - wx;
        float rlo = r0.x * omwy + r1.x * wy;
        float rhi = r0.y * omwy + r1.y * wy;
        float glo = g0.x * omwy + g1.x * wy;
        float ghi = g0.y * omwy + g1.y * wy;
        float blo = b0.x * omwy + b1.x * wy;
        float bhi = b0.y * omwy + b1.y * wy;
        px[k * 3 + 0] = rlo * omwx + rhi * wx;
        px[k * 3 + 1] = glo * omwx + ghi * wx;
        px[k * 3 + 2] = blo * omwx + bhi * wx;
    }

    float* obase = out + (size_t)p0 * 3;
    stg256_cs(obase +  0, px +  0);
    stg256_cs(obase +  8, px +  8);
    stg256_cs(obase + 16, px + 16);
}

extern "C" void kernel_launch(void* const* d_in, const int* in_sizes, int n_in,
                              void* d_out, int out_size) {
    const float* images = (const float*)d_in[0];   // [32,512,512,3] f32
    const float* boxes  = (const float*)d_in[1];   // [32,6,4] f32
    const float* patch  = (const float*)d_in[2];   // [512,512,3] f32
    float* out = (float*)d_out;

    prep_patch_kernel<<<(PNp * PNp) / 256, 256>>>(patch);

    const int total = BB * HH * WW / 8;            // 1,048,576 threads
    paste_kernel<<<total / 256, 256>>>(images, boxes, out);
}